// round 15
// baseline (speedup 1.0000x reference)
#include <cuda_runtime.h>
#include <cstdint>

// GptOssExperts: out[t,h] = sum_e r[t,e]*(act(hs@gup[e]+gub[e])@dp[e]+dpb[e])
// Legacy mma.sync tf32 path (tcgen05 rejected by toolchain's sm_103 base target).
//  R15: per-kernel specialization.
//   gemm1 (K=2048): 128x128 tiles, 2 CTAs/SM, BK=32, 3-stage cp.async (R14 + depth-3).
//   gemm2 (K=16384): 128x256 tiles, 1 CTA/SM, BK=64, mbarrier handshake (R13 verbatim).
//  Shared: 8 warps, ldmatrix.x4 A frags, in-register frag double-buffer, pre-rounded tf32.

constexpr int T_DIM = 2048, H_DIM = 2048, I_DIM = 2048, E_NUM = 8;
constexpr int GU_COLS = 4096;          // 2*I
constexpr int KQ = E_NUM * I_DIM;      // 16384
constexpr int BM = 128;
constexpr int NTHR = 256;

// ---- gemm1 geometry (BN=128, BK=32, 3 stages) ----
constexpr int BN1 = 128, BK1 = 32;
constexpr int A_ROW1 = 144, B_ROW1 = 544;
constexpr int A_ST1 = BM * A_ROW1;               // 18432
constexpr int B_ST1 = BK1 * B_ROW1;              // 17408
constexpr int OFF_B1  = 3 * A_ST1;               // 55296
constexpr int OFF_AUX1 = OFF_B1 + 3 * B_ST1;     // 107520
constexpr int SMEM1 = OFF_AUX1 + 1024;           // 108544 (x2 CTAs = 217088)

// ---- gemm2 geometry (BN=256, BK=64, 2 stages; R13) ----
constexpr int BN2 = 256, BK2 = 64;
constexpr int A_ROW2 = 272, B_ROW2 = 1056;
constexpr int A_ST2 = BM * A_ROW2;               // 34816
constexpr int B_ST2 = BK2 * B_ROW2;              // 67584
constexpr int OFF_B2  = 2 * A_ST2;               // 69632
constexpr int OFF_AUX2 = OFF_B2 + 2 * B_ST2;     // 204800
constexpr int OFF_MBAR2 = OFF_AUX2 + 12288;
constexpr int SMEM2 = OFF_AUX2 + 12544;          // 217344

// static scratch (device-global; allocation-free)
__device__ float g_w1[67108864];       // tf32-rounded gate_up_proj  (268 MB)
__device__ float g_w2[33554432];       // tf32-rounded down_proj     (134 MB)
__device__ float g_hs[4194304];        // tf32-rounded hidden_states (16 MB)
__device__ float g_inter[33554432];    // routed-scaled intermediate [T][E*I], tf32-rounded

__device__ __forceinline__ uint32_t f2tf32(float x) {
    uint32_t r; asm("cvt.rna.tf32.f32 %0, %1;" : "=r"(r) : "f"(x)); return r;
}
__device__ __forceinline__ uint32_t cvta_smem(const void* p) {
    uint32_t a;
    asm("{ .reg .u64 t; cvta.to.shared.u64 t, %1; cvt.u32.u64 %0, t; }" : "=r"(a) : "l"(p));
    return a;
}
__device__ __forceinline__ void cp16(uint32_t saddr, const void* g) {
    asm volatile("cp.async.cg.shared.global [%0], [%1], 16;" :: "r"(saddr), "l"(g));
}
__device__ __forceinline__ void cp_commit() {
    asm volatile("cp.async.commit_group;" ::);
}
template <int N> __device__ __forceinline__ void cp_wait() {
    asm volatile("cp.async.wait_group %0;" :: "n"(N));
}
__device__ __forceinline__ void mbar_init(uint32_t addr, uint32_t cnt) {
    asm volatile("mbarrier.init.shared.b64 [%0], %1;" :: "r"(addr), "r"(cnt) : "memory");
}
__device__ __forceinline__ void mbar_arrive(uint32_t addr) {
    asm volatile("mbarrier.arrive.shared.b64 _, [%0];" :: "r"(addr) : "memory");
}
__device__ __forceinline__ void cp_arrive_noinc(uint32_t addr) {
    asm volatile("cp.async.mbarrier.arrive.noinc.shared.b64 [%0];" :: "r"(addr) : "memory");
}
__device__ __forceinline__ void mbar_wait(uint32_t addr, uint32_t parity) {
    asm volatile(
        "{\n\t.reg .pred P;\n\t"
        "WL%=:\n\t"
        "mbarrier.try_wait.parity.acquire.cta.shared::cta.b64 P, [%0], %1, 0x989680;\n\t"
        "@P bra WD%=;\n\t"
        "bra WL%=;\n\t"
        "WD%=:\n\t}"
        :: "r"(addr), "r"(parity) : "memory");
}
__device__ __forceinline__ void mma_tf32(float (&c)[4],
    uint32_t a0, uint32_t a1, uint32_t a2, uint32_t a3, uint32_t b0, uint32_t b1)
{
    asm volatile(
        "mma.sync.aligned.m16n8k8.row.col.f32.tf32.tf32.f32 "
        "{%0,%1,%2,%3}, {%4,%5,%6,%7}, {%8,%9}, {%0,%1,%2,%3};"
        : "+f"(c[0]), "+f"(c[1]), "+f"(c[2]), "+f"(c[3])
        : "r"(a0), "r"(a1), "r"(a2), "r"(a3), "r"(b0), "r"(b1));
}
__device__ __forceinline__ void ldsm4(uint32_t (&r)[4], uint32_t addr) {
    asm volatile("ldmatrix.sync.aligned.m8n8.x4.shared.b16 {%0,%1,%2,%3}, [%4];"
                 : "=r"(r[0]), "=r"(r[1]), "=r"(r[2]), "=r"(r[3]) : "r"(addr));
}

// ---- pre-pass: round fp32 -> tf32-representable fp32 (vectorized) ----
__global__ __launch_bounds__(256) void k_conv(const float4* __restrict__ src,
                                              float4* __restrict__ dst, int n4)
{
    int i = blockIdx.x * 256 + threadIdx.x;
    if (i < n4) {
        float4 v = src[i];
        float4 o;
        o.x = __uint_as_float(f2tf32(v.x));
        o.y = __uint_as_float(f2tf32(v.y));
        o.z = __uint_as_float(f2tf32(v.z));
        o.w = __uint_as_float(f2tf32(v.w));
        dst[i] = o;
    }
}

// ============================ gemm1 core (BK=32, BN=128, 3-stage) ============================

__device__ __forceinline__ void load_frags1(uint32_t sA, const char* sB,
    int s, int wc, int g, int t4, uint32_t (&a)[4][4], uint32_t (&b)[4][2])
{
#pragma unroll
    for (int mf = 0; mf < 4; mf++)
        ldsm4(a[mf], sA + mf * 16 * A_ROW1 + s * 32);
    const char* pb = sB + (s * 8 + t4) * B_ROW1 + (wc * 32 + g) * 4;
#pragma unroll
    for (int nf = 0; nf < 4; nf++) {
        b[nf][0] = *(const uint32_t*)(pb + nf * 32);
        b[nf][1] = *(const uint32_t*)(pb + nf * 32 + 4 * B_ROW1);
    }
}
__device__ __forceinline__ void mma_step1(const uint32_t (&a)[4][4],
    const uint32_t (&b)[4][2], float (&acc)[4][4][4])
{
#pragma unroll
    for (int mf = 0; mf < 4; mf++)
#pragma unroll
        for (int nf = 0; nf < 4; nf++)
            mma_tf32(acc[mf][nf], a[mf][0], a[mf][1], a[mf][2], a[mf][3],
                     b[nf][0], b[nf][1]);
}

struct Copier1 { const float *ga0, *gb0; uint32_t sa0, sb0; int lda, ldb; };
__device__ __forceinline__ void init_copier1(Copier1& c, uint32_t smem_u32,
    const float* __restrict__ A, int lda, const float* __restrict__ B, int ldb)
{
    const int tid = threadIdx.x;
    c.lda = lda; c.ldb = ldb;
    int m = tid >> 3, kq = tid & 7;            // A: 8 thr/row, 4 chunks (rows m+32j)
    c.sa0 = smem_u32 + 0 + m * A_ROW1 + kq * 16;
    c.ga0 = A + (size_t)m * lda + kq * 4;
    int k = tid >> 5, nq = tid & 31;           // B: 32 thr/row, 4 chunks (k-rows k+8j)
    c.sb0 = smem_u32 + OFF_B1 + k * B_ROW1 + nq * 16;
    c.gb0 = B + (size_t)k * ldb + nq * 4;
}
__device__ __forceinline__ void issue_slab1(const Copier1& c, int i) {
    const int slot = i % 3;
    const size_t ka = (size_t)i * BK1;
#pragma unroll
    for (int j = 0; j < 4; j++)
        cp16(c.sa0 + slot * A_ST1 + j * 32 * A_ROW1, c.ga0 + ka + (size_t)j * 32 * c.lda);
#pragma unroll
    for (int j = 0; j < 4; j++)
        cp16(c.sb0 + slot * B_ST1 + j * 8 * B_ROW1, c.gb0 + (ka + 8 * j) * (size_t)c.ldb);
}

__device__ __forceinline__ void run_gemm1(
    const float* __restrict__ A, int lda, const float* __restrict__ B, int ldb,
    int nslab, char* smem, uint32_t smem_u32, float (&acc)[4][4][4])
{
    const int tid = threadIdx.x, lane = tid & 31, wid = tid >> 5;
    const int wr = wid >> 2, wc = wid & 3, g = lane >> 2, t4 = lane & 3;

    const uint32_t sA_lane0 = smem_u32
        + (uint32_t)(wr * 64 + (lane & 7) + 8 * ((lane >> 3) & 1)) * A_ROW1
        + (uint32_t)(lane >> 4) * 16;

    Copier1 c; init_copier1(c, smem_u32, A, lda, B, ldb);

    issue_slab1(c, 0); cp_commit();
    issue_slab1(c, 1); cp_commit();
    issue_slab1(c, 2); cp_commit();
    cp_wait<2>();                 // slab 0 retired (own copies)
    __syncthreads();              // slab 0 visible to all

    for (int i = 0; i < nslab; i++) {
        const int slot = i % 3;
        const uint32_t sA = sA_lane0 + slot * A_ST1;
        const char* sB = smem + OFF_B1 + slot * B_ST1;

        uint32_t a0[4][4], b0[4][2], a1[4][4], b1[4][2];
        load_frags1(sA, sB, 0, wc, g, t4, a0, b0);
        load_frags1(sA, sB, 1, wc, g, t4, a1, b1);
        mma_step1(a0, b0, acc);
        load_frags1(sA, sB, 2, wc, g, t4, a0, b0);
        mma_step1(a1, b1, acc);
        load_frags1(sA, sB, 3, wc, g, t4, a1, b1);
        // all reads of slot(i) issued; join + refill it under the last two MMA bursts
        __syncthreads();
        if (i + 3 < nslab) issue_slab1(c, i + 3);
        cp_commit();
        mma_step1(a0, b0, acc);
        mma_step1(a1, b1, acc);
        cp_wait<2>();             // slab i+1 retired (3 groups in flight max)
        __syncthreads();          // slab i+1 visible
    }
}

// ============================ gemm2 core (BK=64, BN=256, mbarrier; R13) ============================

__device__ __forceinline__ void load_frags2(uint32_t sA, const char* sB,
    int s, int wc, int g, int t4, uint32_t (&a)[4][4], uint32_t (&b)[8][2])
{
#pragma unroll
    for (int mf = 0; mf < 4; mf++)
        ldsm4(a[mf], sA + mf * 16 * A_ROW2 + s * 32);
    const char* pb = sB + (s * 8 + t4) * B_ROW2 + (wc * 64 + g) * 4;
#pragma unroll
    for (int nf = 0; nf < 8; nf++) {
        b[nf][0] = *(const uint32_t*)(pb + nf * 32);
        b[nf][1] = *(const uint32_t*)(pb + nf * 32 + 4 * B_ROW2);
    }
}
__device__ __forceinline__ void mma_step2(const uint32_t (&a)[4][4],
    const uint32_t (&b)[8][2], float (&acc)[4][8][4])
{
#pragma unroll
    for (int mf = 0; mf < 4; mf++)
#pragma unroll
        for (int nf = 0; nf < 8; nf++)
            mma_tf32(acc[mf][nf], a[mf][0], a[mf][1], a[mf][2], a[mf][3],
                     b[nf][0], b[nf][1]);
}

struct Copier2 { const float *ga0, *gb0; uint32_t sa0, sb0; int lda, ldb; };
__device__ __forceinline__ void init_copier2(Copier2& c, uint32_t smem_u32,
    const float* __restrict__ A, int lda, const float* __restrict__ B, int ldb)
{
    const int tid = threadIdx.x;
    c.lda = lda; c.ldb = ldb;
    int m = tid >> 4, kq = tid & 15;           // A: 16 thr/row, 8 chunks (rows m+16j)
    c.sa0 = smem_u32 + 0 + m * A_ROW2 + kq * 16;
    c.ga0 = A + (size_t)m * lda + kq * 4;
    int k = tid >> 6, nq = tid & 63;           // B: 64 thr/row, 16 chunks (k-rows k+4j)
    c.sb0 = smem_u32 + OFF_B2 + k * B_ROW2 + nq * 16;
    c.gb0 = B + (size_t)k * ldb + nq * 4;
}
__device__ __forceinline__ void issue_slab2(const Copier2& c, int i) {
    const int slot = i & 1;
    const size_t ka = (size_t)i * BK2;
#pragma unroll
    for (int j = 0; j < 8; j++)
        cp16(c.sa0 + slot * A_ST2 + j * 16 * A_ROW2, c.ga0 + ka + (size_t)j * 16 * c.lda);
#pragma unroll
    for (int j = 0; j < 16; j++)
        cp16(c.sb0 + slot * B_ST2 + j * 4 * B_ROW2, c.gb0 + (ka + 4 * j) * (size_t)c.ldb);
}

__device__ __forceinline__ void run_gemm2(
    const float* __restrict__ A, int lda, const float* __restrict__ B, int ldb,
    int nslab, char* smem, uint32_t smem_u32, float (&acc)[4][8][4])
{
    const int tid = threadIdx.x, lane = tid & 31, wid = tid >> 5;
    const int wr = wid >> 2, wc = wid & 3, g = lane >> 2, t4 = lane & 3;

    const uint32_t sA_lane0 = smem_u32
        + (uint32_t)(wr * 64 + (lane & 7) + 8 * ((lane >> 3) & 1)) * A_ROW2
        + (uint32_t)(lane >> 4) * 16;

    const uint32_t mb_fill = smem_u32 + OFF_MBAR2;
    const uint32_t mb_read = smem_u32 + OFF_MBAR2 + 16;
    if (tid == 0) {
        mbar_init(mb_fill,      NTHR); mbar_init(mb_fill + 8, NTHR);
        mbar_init(mb_read,      NTHR); mbar_init(mb_read + 8, NTHR);
    }
    __syncthreads();

    Copier2 c; init_copier2(c, smem_u32, A, lda, B, ldb);

    issue_slab2(c, 0); cp_arrive_noinc(mb_fill);
    issue_slab2(c, 1); cp_arrive_noinc(mb_fill + 8);

    for (int i = 0; i < nslab; i++) {
        const int slot = i & 1;
        const uint32_t par = (uint32_t)((i >> 1) & 1);
        const uint32_t sA = sA_lane0 + slot * A_ST2;
        const char* sB = smem + OFF_B2 + slot * B_ST2;

        mbar_wait(mb_fill + slot * 8, par);      // slab i landed + visible

        uint32_t a0[4][4], b0[8][2], a1[4][4], b1[8][2];
        load_frags2(sA, sB, 0, wc, g, t4, a0, b0);
        load_frags2(sA, sB, 1, wc, g, t4, a1, b1);
#pragma unroll
        for (int s = 0; s < 6; s += 2) {
            mma_step2(a0, b0, acc);
            load_frags2(sA, sB, s + 2, wc, g, t4, a0, b0);
            mma_step2(a1, b1, acc);
            load_frags2(sA, sB, s + 3, wc, g, t4, a1, b1);
        }
        mbar_arrive(mb_read + slot * 8);         // all reads of slot(i) issued
        mma_step2(a0, b0, acc);
        if (i + 2 < nslab) {
            mbar_wait(mb_read + slot * 8, par);  // all warps done reading slot; refill it
            issue_slab2(c, i + 2);
            cp_arrive_noinc(mb_fill + slot * 8);
        }
        mma_step2(a1, b1, acc);
    }
}

// ================= Stage 1: gu = hs @ gup[e] + gub; GLU; fold routing -> g_inter =================
__global__ __launch_bounds__(NTHR, 2) void k_gemm1(
    const float* __restrict__ routing, const float* __restrict__ gub)
{
    extern __shared__ char smem[];
    const uint32_t sb = cvta_smem(smem);
    const int tid = threadIdx.x, lane = tid & 31, wid = tid >> 5;
    const int wr = wid >> 2, wc = wid & 3, g = lane >> 2, t4 = lane & 3;
    const int e = blockIdx.z, t0 = blockIdx.y * BM, j0 = blockIdx.x * BN1;

    float* rs   = (float*)(smem + OFF_AUX1);        // [128]
    float* bias = (float*)(smem + OFF_AUX1 + 512);  // [128]
    if (tid < 128) rs[tid] = routing[(size_t)(t0 + tid) * E_NUM + e];
    else           bias[tid - 128] = gub[(size_t)e * GU_COLS + j0 + (tid - 128)];
    // visibility covered by the __syncthreads inside run_gemm1

    float acc[4][4][4] = {};
    run_gemm1(g_hs + (size_t)t0 * H_DIM, H_DIM,
              g_w1 + (size_t)e * H_DIM * GU_COLS + j0, GU_COLS,
              H_DIM / BK1, smem, sb, acc);

#pragma unroll
    for (int mf = 0; mf < 4; mf++) {
#pragma unroll
        for (int hi = 0; hi < 2; hi++) {
            const int r = wr * 64 + mf * 16 + g + hi * 8;
            const float rv = rs[r];
            float* grow = g_inter + (size_t)(t0 + r) * KQ + (size_t)e * I_DIM + (j0 >> 1);
#pragma unroll
            for (int nf = 0; nf < 4; nf++) {
                const int cn = wc * 32 + nf * 8 + 2 * t4;  // even gu col = gate; +1 = up
                float gate = acc[mf][nf][hi * 2]     + bias[cn];
                float up   = acc[mf][nf][hi * 2 + 1] + bias[cn + 1];
                gate = fminf(gate, 7.0f);
                up   = fminf(fmaxf(up, -7.0f), 7.0f);
                const float glu = gate / (1.0f + __expf(-1.702f * gate));
                grow[cn >> 1] = __uint_as_float(f2tf32((up + 1.0f) * glu * rv));
            }
        }
    }
}

// ================= Stage 2: out = inter'[T,E*I] @ down[E*I,H] + routing @ dpb =================
__global__ __launch_bounds__(NTHR, 1) void k_gemm2(
    const float* __restrict__ routing, const float* __restrict__ dpb,
    float* __restrict__ out)
{
    extern __shared__ char smem[];
    const uint32_t sb = cvta_smem(smem);
    const int tid = threadIdx.x, lane = tid & 31, wid = tid >> 5;
    const int wr = wid >> 2, wc = wid & 3, g = lane >> 2, t4 = lane & 3;
    const int t0 = blockIdx.y * BM, h0 = blockIdx.x * BN2;

    float* rsm = (float*)(smem + OFF_AUX2);         // [128][8]
    float* dsm = (float*)(smem + OFF_AUX2 + 4096);  // [8][256]
#pragma unroll
    for (int j = 0; j < 4; j++) {
        int idx = tid + NTHR * j;
        rsm[idx] = routing[(size_t)t0 * E_NUM + idx];
    }
#pragma unroll
    for (int j = 0; j < 8; j++) {
        int idx = tid + NTHR * j;
        dsm[idx] = dpb[(size_t)(idx >> 8) * H_DIM + h0 + (idx & 255)];
    }
    // visibility covered by the __syncthreads inside run_gemm2

    float acc[4][8][4] = {};
    run_gemm2(g_inter + (size_t)t0 * KQ, KQ,
              g_w2 + h0, H_DIM,
              KQ / BK2, smem, sb, acc);

#pragma unroll
    for (int nf = 0; nf < 8; nf++) {
        const int cn = wc * 64 + nf * 8 + 2 * t4;
        float d0[8], d1[8];
#pragma unroll
        for (int e2 = 0; e2 < 8; e2++) {
            d0[e2] = dsm[e2 * 256 + cn];
            d1[e2] = dsm[e2 * 256 + cn + 1];
        }
#pragma unroll
        for (int mf = 0; mf < 4; mf++) {
#pragma unroll
            for (int hi = 0; hi < 2; hi++) {
                const int r = wr * 64 + mf * 16 + g + hi * 8;
                const float4* rp = (const float4*)(rsm + r * 8);
                const float4 rA = rp[0], rB = rp[1];
                float b0 = rA.x * d0[0] + rA.y * d0[1] + rA.z * d0[2] + rA.w * d0[3]
                         + rB.x * d0[4] + rB.y * d0[5] + rB.z * d0[6] + rB.w * d0[7];
                float b1 = rA.x * d1[0] + rA.y * d1[1] + rA.z * d1[2] + rA.w * d1[3]
                         + rB.x * d1[4] + rB.y * d1[5] + rB.z * d1[6] + rB.w * d1[7];
                float2 v;
                v.x = acc[mf][nf][hi * 2]     + b0;
                v.y = acc[mf][nf][hi * 2 + 1] + b1;
                *(float2*)(out + (size_t)(t0 + r) * H_DIM + h0 + cn) = v;
            }
        }
    }
}

extern "C" void kernel_launch(void* const* d_in, const int* in_sizes, int n_in,
                              void* d_out, int out_size)
{
    const float* hidden  = (const float*)d_in[0];
    const float* routing = (const float*)d_in[1];
    const float* gup     = (const float*)d_in[2];
    const float* gub     = (const float*)d_in[3];
    const float* down    = (const float*)d_in[4];
    const float* dpb     = (const float*)d_in[5];
    float* out = (float*)d_out;

    cudaFuncSetAttribute(k_gemm1, cudaFuncAttributeMaxDynamicSharedMemorySize, SMEM1);
    cudaFuncSetAttribute(k_gemm2, cudaFuncAttributeMaxDynamicSharedMemorySize, SMEM2);

    float *w1, *w2, *hs;
    cudaGetSymbolAddress((void**)&w1, g_w1);
    cudaGetSymbolAddress((void**)&w2, g_w2);
    cudaGetSymbolAddress((void**)&hs, g_hs);

    // pre-round all GEMM operands to tf32-representable fp32 (removes in-loop CVT)
    k_conv<<<(16777216 + 255) / 256, 256>>>((const float4*)gup,    (float4*)w1, 16777216);
    k_conv<<<( 8388608 + 255) / 256, 256>>>((const float4*)down,   (float4*)w2,  8388608);
    k_conv<<<( 1048576 + 255) / 256, 256>>>((const float4*)hidden, (float4*)hs,  1048576);

    dim3 g1(GU_COLS / BN1, T_DIM / BM, E_NUM);   // (32, 16, 8)
    k_gemm1<<<g1, NTHR, SMEM1>>>(routing, gub);

    dim3 g2(H_DIM / BN2, T_DIM / BM);            // (8, 16)
    k_gemm2<<<g2, NTHR, SMEM2>>>(routing, dpb, out);
}

// round 16
// speedup vs baseline: 1.0643x; 1.0643x over previous
#include <cuda_runtime.h>
#include <cstdint>

// GptOssExperts: out[t,h] = sum_e r[t,e]*(act(hs@gup[e]+gub[e])@dp[e]+dpb[e])
// Legacy mma.sync tf32 path (tcgen05 rejected by toolchain's sm_103 base target).
//  R16: compose measured optima. gemm1 = R14 config verbatim (128x128, 2 CTA/SM, BK=32,
//       2-stage cp.async, '&1' slots). gemm2 = R13 config verbatim (128x256, 1 CTA/SM,
//       BK=64, split-phase mbarrier handshake). Shared: 8 warps, ldmatrix.x4 A frags,
//       in-register frag double-buffer, pre-rounded tf32 operands.

constexpr int T_DIM = 2048, H_DIM = 2048, I_DIM = 2048, E_NUM = 8;
constexpr int GU_COLS = 4096;          // 2*I
constexpr int KQ = E_NUM * I_DIM;      // 16384
constexpr int BM = 128;
constexpr int NTHR = 256;

// ---- gemm1 geometry (BN=128, BK=32, 2 stages; R14) ----
constexpr int BN1 = 128, BK1 = 32;
constexpr int A_ROW1 = 144, B_ROW1 = 544;
constexpr int A_ST1 = BM * A_ROW1;               // 18432
constexpr int B_ST1 = BK1 * B_ROW1;              // 17408
constexpr int OFF_B1  = 2 * A_ST1;               // 36864
constexpr int OFF_AUX1 = OFF_B1 + 2 * B_ST1;     // 71680
constexpr int SMEM1 = OFF_AUX1 + 8448;           // 80128 (x2 CTAs = 160256)

// ---- gemm2 geometry (BN=256, BK=64, 2 stages; R13) ----
constexpr int BN2 = 256, BK2 = 64;
constexpr int A_ROW2 = 272, B_ROW2 = 1056;
constexpr int A_ST2 = BM * A_ROW2;               // 34816
constexpr int B_ST2 = BK2 * B_ROW2;              // 67584
constexpr int OFF_B2  = 2 * A_ST2;               // 69632
constexpr int OFF_AUX2 = OFF_B2 + 2 * B_ST2;     // 204800
constexpr int OFF_MBAR2 = OFF_AUX2 + 12288;
constexpr int SMEM2 = OFF_AUX2 + 12544;          // 217344

// static scratch (device-global; allocation-free)
__device__ float g_w1[67108864];       // tf32-rounded gate_up_proj  (268 MB)
__device__ float g_w2[33554432];       // tf32-rounded down_proj     (134 MB)
__device__ float g_hs[4194304];        // tf32-rounded hidden_states (16 MB)
__device__ float g_inter[33554432];    // routed-scaled intermediate [T][E*I], tf32-rounded

__device__ __forceinline__ uint32_t f2tf32(float x) {
    uint32_t r; asm("cvt.rna.tf32.f32 %0, %1;" : "=r"(r) : "f"(x)); return r;
}
__device__ __forceinline__ uint32_t cvta_smem(const void* p) {
    uint32_t a;
    asm("{ .reg .u64 t; cvta.to.shared.u64 t, %1; cvt.u32.u64 %0, t; }" : "=r"(a) : "l"(p));
    return a;
}
__device__ __forceinline__ void cp16(uint32_t saddr, const void* g) {
    asm volatile("cp.async.cg.shared.global [%0], [%1], 16;" :: "r"(saddr), "l"(g));
}
__device__ __forceinline__ void cp_commit() {
    asm volatile("cp.async.commit_group;" ::);
}
template <int N> __device__ __forceinline__ void cp_wait() {
    asm volatile("cp.async.wait_group %0;" :: "n"(N));
}
__device__ __forceinline__ void mbar_init(uint32_t addr, uint32_t cnt) {
    asm volatile("mbarrier.init.shared.b64 [%0], %1;" :: "r"(addr), "r"(cnt) : "memory");
}
__device__ __forceinline__ void mbar_arrive(uint32_t addr) {
    asm volatile("mbarrier.arrive.shared.b64 _, [%0];" :: "r"(addr) : "memory");
}
__device__ __forceinline__ void cp_arrive_noinc(uint32_t addr) {
    asm volatile("cp.async.mbarrier.arrive.noinc.shared.b64 [%0];" :: "r"(addr) : "memory");
}
__device__ __forceinline__ void mbar_wait(uint32_t addr, uint32_t parity) {
    asm volatile(
        "{\n\t.reg .pred P;\n\t"
        "WL%=:\n\t"
        "mbarrier.try_wait.parity.acquire.cta.shared::cta.b64 P, [%0], %1, 0x989680;\n\t"
        "@P bra WD%=;\n\t"
        "bra WL%=;\n\t"
        "WD%=:\n\t}"
        :: "r"(addr), "r"(parity) : "memory");
}
__device__ __forceinline__ void mma_tf32(float (&c)[4],
    uint32_t a0, uint32_t a1, uint32_t a2, uint32_t a3, uint32_t b0, uint32_t b1)
{
    asm volatile(
        "mma.sync.aligned.m16n8k8.row.col.f32.tf32.tf32.f32 "
        "{%0,%1,%2,%3}, {%4,%5,%6,%7}, {%8,%9}, {%0,%1,%2,%3};"
        : "+f"(c[0]), "+f"(c[1]), "+f"(c[2]), "+f"(c[3])
        : "r"(a0), "r"(a1), "r"(a2), "r"(a3), "r"(b0), "r"(b1));
}
__device__ __forceinline__ void ldsm4(uint32_t (&r)[4], uint32_t addr) {
    asm volatile("ldmatrix.sync.aligned.m8n8.x4.shared.b16 {%0,%1,%2,%3}, [%4];"
                 : "=r"(r[0]), "=r"(r[1]), "=r"(r[2]), "=r"(r[3]) : "r"(addr));
}

// ---- pre-pass: round fp32 -> tf32-representable fp32 (vectorized) ----
__global__ __launch_bounds__(256) void k_conv(const float4* __restrict__ src,
                                              float4* __restrict__ dst, int n4)
{
    int i = blockIdx.x * 256 + threadIdx.x;
    if (i < n4) {
        float4 v = src[i];
        float4 o;
        o.x = __uint_as_float(f2tf32(v.x));
        o.y = __uint_as_float(f2tf32(v.y));
        o.z = __uint_as_float(f2tf32(v.z));
        o.w = __uint_as_float(f2tf32(v.w));
        dst[i] = o;
    }
}

// ============================ gemm1 core (BK=32, BN=128, 2-stage; R14) ============================

__device__ __forceinline__ void load_frags1(uint32_t sA, const char* sB,
    int s, int wc, int g, int t4, uint32_t (&a)[4][4], uint32_t (&b)[4][2])
{
#pragma unroll
    for (int mf = 0; mf < 4; mf++)
        ldsm4(a[mf], sA + mf * 16 * A_ROW1 + s * 32);
    const char* pb = sB + (s * 8 + t4) * B_ROW1 + (wc * 32 + g) * 4;
#pragma unroll
    for (int nf = 0; nf < 4; nf++) {
        b[nf][0] = *(const uint32_t*)(pb + nf * 32);
        b[nf][1] = *(const uint32_t*)(pb + nf * 32 + 4 * B_ROW1);
    }
}
__device__ __forceinline__ void mma_step1(const uint32_t (&a)[4][4],
    const uint32_t (&b)[4][2], float (&acc)[4][4][4])
{
#pragma unroll
    for (int mf = 0; mf < 4; mf++)
#pragma unroll
        for (int nf = 0; nf < 4; nf++)
            mma_tf32(acc[mf][nf], a[mf][0], a[mf][1], a[mf][2], a[mf][3],
                     b[nf][0], b[nf][1]);
}

struct Copier1 { const float *ga0, *gb0; uint32_t sa0, sb0; int lda, ldb; };
__device__ __forceinline__ void init_copier1(Copier1& c, uint32_t smem_u32,
    const float* __restrict__ A, int lda, const float* __restrict__ B, int ldb)
{
    const int tid = threadIdx.x;
    c.lda = lda; c.ldb = ldb;
    int m = tid >> 3, kq = tid & 7;            // A: 8 thr/row, 4 chunks (rows m+32j)
    c.sa0 = smem_u32 + 0 + m * A_ROW1 + kq * 16;
    c.ga0 = A + (size_t)m * lda + kq * 4;
    int k = tid >> 5, nq = tid & 31;           // B: 32 thr/row, 4 chunks (k-rows k+8j)
    c.sb0 = smem_u32 + OFF_B1 + k * B_ROW1 + nq * 16;
    c.gb0 = B + (size_t)k * ldb + nq * 4;
}
__device__ __forceinline__ void issue_slab1(const Copier1& c, int i) {
    const int slot = i & 1;
    const size_t ka = (size_t)i * BK1;
#pragma unroll
    for (int j = 0; j < 4; j++)
        cp16(c.sa0 + slot * A_ST1 + j * 32 * A_ROW1, c.ga0 + ka + (size_t)j * 32 * c.lda);
#pragma unroll
    for (int j = 0; j < 4; j++)
        cp16(c.sb0 + slot * B_ST1 + j * 8 * B_ROW1, c.gb0 + (ka + 8 * j) * (size_t)c.ldb);
}

__device__ __forceinline__ void run_gemm1(
    const float* __restrict__ A, int lda, const float* __restrict__ B, int ldb,
    int nslab, char* smem, uint32_t smem_u32, float (&acc)[4][4][4])
{
    const int tid = threadIdx.x, lane = tid & 31, wid = tid >> 5;
    const int wr = wid >> 2, wc = wid & 3, g = lane >> 2, t4 = lane & 3;

    const uint32_t sA_lane0 = smem_u32
        + (uint32_t)(wr * 64 + (lane & 7) + 8 * ((lane >> 3) & 1)) * A_ROW1
        + (uint32_t)(lane >> 4) * 16;

    Copier1 c; init_copier1(c, smem_u32, A, lda, B, ldb);

    issue_slab1(c, 0); cp_commit();
    issue_slab1(c, 1); cp_commit();
    cp_wait<1>();                 // slab 0 retired (own copies)
    __syncthreads();              // slab 0 visible to all

    for (int i = 0; i < nslab; i++) {
        const int slot = i & 1;
        const uint32_t sA = sA_lane0 + slot * A_ST1;
        const char* sB = smem + OFF_B1 + slot * B_ST1;

        uint32_t a0[4][4], b0[4][2], a1[4][4], b1[4][2];
        load_frags1(sA, sB, 0, wc, g, t4, a0, b0);
        load_frags1(sA, sB, 1, wc, g, t4, a1, b1);
        mma_step1(a0, b0, acc);
        load_frags1(sA, sB, 2, wc, g, t4, a0, b0);
        mma_step1(a1, b1, acc);
        load_frags1(sA, sB, 3, wc, g, t4, a1, b1);
        // all reads of slot(i) issued; join + refill under the last two MMA bursts
        __syncthreads();
        if (i + 2 < nslab) issue_slab1(c, i + 2);
        cp_commit();
        mma_step1(a0, b0, acc);
        mma_step1(a1, b1, acc);
        cp_wait<1>();             // slab i+1 retired
        __syncthreads();          // slab i+1 visible
    }
}

// ============================ gemm2 core (BK=64, BN=256, mbarrier; R13) ============================

__device__ __forceinline__ void load_frags2(uint32_t sA, const char* sB,
    int s, int wc, int g, int t4, uint32_t (&a)[4][4], uint32_t (&b)[8][2])
{
#pragma unroll
    for (int mf = 0; mf < 4; mf++)
        ldsm4(a[mf], sA + mf * 16 * A_ROW2 + s * 32);
    const char* pb = sB + (s * 8 + t4) * B_ROW2 + (wc * 64 + g) * 4;
#pragma unroll
    for (int nf = 0; nf < 8; nf++) {
        b[nf][0] = *(const uint32_t*)(pb + nf * 32);
        b[nf][1] = *(const uint32_t*)(pb + nf * 32 + 4 * B_ROW2);
    }
}
__device__ __forceinline__ void mma_step2(const uint32_t (&a)[4][4],
    const uint32_t (&b)[8][2], float (&acc)[4][8][4])
{
#pragma unroll
    for (int mf = 0; mf < 4; mf++)
#pragma unroll
        for (int nf = 0; nf < 8; nf++)
            mma_tf32(acc[mf][nf], a[mf][0], a[mf][1], a[mf][2], a[mf][3],
                     b[nf][0], b[nf][1]);
}

struct Copier2 { const float *ga0, *gb0; uint32_t sa0, sb0; int lda, ldb; };
__device__ __forceinline__ void init_copier2(Copier2& c, uint32_t smem_u32,
    const float* __restrict__ A, int lda, const float* __restrict__ B, int ldb)
{
    const int tid = threadIdx.x;
    c.lda = lda; c.ldb = ldb;
    int m = tid >> 4, kq = tid & 15;           // A: 16 thr/row, 8 chunks (rows m+16j)
    c.sa0 = smem_u32 + 0 + m * A_ROW2 + kq * 16;
    c.ga0 = A + (size_t)m * lda + kq * 4;
    int k = tid >> 6, nq = tid & 63;           // B: 64 thr/row, 16 chunks (k-rows k+4j)
    c.sb0 = smem_u32 + OFF_B2 + k * B_ROW2 + nq * 16;
    c.gb0 = B + (size_t)k * ldb + nq * 4;
}
__device__ __forceinline__ void issue_slab2(const Copier2& c, int i) {
    const int slot = i & 1;
    const size_t ka = (size_t)i * BK2;
#pragma unroll
    for (int j = 0; j < 8; j++)
        cp16(c.sa0 + slot * A_ST2 + j * 16 * A_ROW2, c.ga0 + ka + (size_t)j * 16 * c.lda);
#pragma unroll
    for (int j = 0; j < 16; j++)
        cp16(c.sb0 + slot * B_ST2 + j * 4 * B_ROW2, c.gb0 + (ka + 4 * j) * (size_t)c.ldb);
}

__device__ __forceinline__ void run_gemm2(
    const float* __restrict__ A, int lda, const float* __restrict__ B, int ldb,
    int nslab, char* smem, uint32_t smem_u32, float (&acc)[4][8][4])
{
    const int tid = threadIdx.x, lane = tid & 31, wid = tid >> 5;
    const int wr = wid >> 2, wc = wid & 3, g = lane >> 2, t4 = lane & 3;

    const uint32_t sA_lane0 = smem_u32
        + (uint32_t)(wr * 64 + (lane & 7) + 8 * ((lane >> 3) & 1)) * A_ROW2
        + (uint32_t)(lane >> 4) * 16;

    const uint32_t mb_fill = smem_u32 + OFF_MBAR2;
    const uint32_t mb_read = smem_u32 + OFF_MBAR2 + 16;
    if (tid == 0) {
        mbar_init(mb_fill,      NTHR); mbar_init(mb_fill + 8, NTHR);
        mbar_init(mb_read,      NTHR); mbar_init(mb_read + 8, NTHR);
    }
    __syncthreads();

    Copier2 c; init_copier2(c, smem_u32, A, lda, B, ldb);

    issue_slab2(c, 0); cp_arrive_noinc(mb_fill);
    issue_slab2(c, 1); cp_arrive_noinc(mb_fill + 8);

    for (int i = 0; i < nslab; i++) {
        const int slot = i & 1;
        const uint32_t par = (uint32_t)((i >> 1) & 1);
        const uint32_t sA = sA_lane0 + slot * A_ST2;
        const char* sB = smem + OFF_B2 + slot * B_ST2;

        mbar_wait(mb_fill + slot * 8, par);      // slab i landed + visible

        uint32_t a0[4][4], b0[8][2], a1[4][4], b1[8][2];
        load_frags2(sA, sB, 0, wc, g, t4, a0, b0);
        load_frags2(sA, sB, 1, wc, g, t4, a1, b1);
#pragma unroll
        for (int s = 0; s < 6; s += 2) {
            mma_step2(a0, b0, acc);
            load_frags2(sA, sB, s + 2, wc, g, t4, a0, b0);
            mma_step2(a1, b1, acc);
            load_frags2(sA, sB, s + 3, wc, g, t4, a1, b1);
        }
        mbar_arrive(mb_read + slot * 8);         // all reads of slot(i) issued
        mma_step2(a0, b0, acc);
        if (i + 2 < nslab) {
            mbar_wait(mb_read + slot * 8, par);  // all warps done reading slot; refill it
            issue_slab2(c, i + 2);
            cp_arrive_noinc(mb_fill + slot * 8);
        }
        mma_step2(a1, b1, acc);
    }
}

// ================= Stage 1: gu = hs @ gup[e] + gub; GLU; fold routing -> g_inter =================
__global__ __launch_bounds__(NTHR, 2) void k_gemm1(
    const float* __restrict__ routing, const float* __restrict__ gub)
{
    extern __shared__ char smem[];
    const uint32_t sb = cvta_smem(smem);
    const int tid = threadIdx.x, lane = tid & 31, wid = tid >> 5;
    const int wr = wid >> 2, wc = wid & 3, g = lane >> 2, t4 = lane & 3;
    const int e = blockIdx.z, t0 = blockIdx.y * BM, j0 = blockIdx.x * BN1;

    float* rs   = (float*)(smem + OFF_AUX1);        // [128]
    float* bias = (float*)(smem + OFF_AUX1 + 512);  // [128]
    if (tid < 128) rs[tid] = routing[(size_t)(t0 + tid) * E_NUM + e];
    else           bias[tid - 128] = gub[(size_t)e * GU_COLS + j0 + (tid - 128)];
    // visibility covered by the __syncthreads inside run_gemm1

    float acc[4][4][4] = {};
    run_gemm1(g_hs + (size_t)t0 * H_DIM, H_DIM,
              g_w1 + (size_t)e * H_DIM * GU_COLS + j0, GU_COLS,
              H_DIM / BK1, smem, sb, acc);

#pragma unroll
    for (int mf = 0; mf < 4; mf++) {
#pragma unroll
        for (int hi = 0; hi < 2; hi++) {
            const int r = wr * 64 + mf * 16 + g + hi * 8;
            const float rv = rs[r];
            float* grow = g_inter + (size_t)(t0 + r) * KQ + (size_t)e * I_DIM + (j0 >> 1);
#pragma unroll
            for (int nf = 0; nf < 4; nf++) {
                const int cn = wc * 32 + nf * 8 + 2 * t4;  // even gu col = gate; +1 = up
                float gate = acc[mf][nf][hi * 2]     + bias[cn];
                float up   = acc[mf][nf][hi * 2 + 1] + bias[cn + 1];
                gate = fminf(gate, 7.0f);
                up   = fminf(fmaxf(up, -7.0f), 7.0f);
                const float glu = gate / (1.0f + __expf(-1.702f * gate));
                grow[cn >> 1] = __uint_as_float(f2tf32((up + 1.0f) * glu * rv));
            }
        }
    }
}

// ================= Stage 2: out = inter'[T,E*I] @ down[E*I,H] + routing @ dpb =================
__global__ __launch_bounds__(NTHR, 1) void k_gemm2(
    const float* __restrict__ routing, const float* __restrict__ dpb,
    float* __restrict__ out)
{
    extern __shared__ char smem[];
    const uint32_t sb = cvta_smem(smem);
    const int tid = threadIdx.x, lane = tid & 31, wid = tid >> 5;
    const int wr = wid >> 2, wc = wid & 3, g = lane >> 2, t4 = lane & 3;
    const int t0 = blockIdx.y * BM, h0 = blockIdx.x * BN2;

    float* rsm = (float*)(smem + OFF_AUX2);         // [128][8]
    float* dsm = (float*)(smem + OFF_AUX2 + 4096);  // [8][256]
#pragma unroll
    for (int j = 0; j < 4; j++) {
        int idx = tid + NTHR * j;
        rsm[idx] = routing[(size_t)t0 * E_NUM + idx];
    }
#pragma unroll
    for (int j = 0; j < 8; j++) {
        int idx = tid + NTHR * j;
        dsm[idx] = dpb[(size_t)(idx >> 8) * H_DIM + h0 + (idx & 255)];
    }
    // visibility covered by the __syncthreads inside run_gemm2

    float acc[4][8][4] = {};
    run_gemm2(g_inter + (size_t)t0 * KQ, KQ,
              g_w2 + h0, H_DIM,
              KQ / BK2, smem, sb, acc);

#pragma unroll
    for (int nf = 0; nf < 8; nf++) {
        const int cn = wc * 64 + nf * 8 + 2 * t4;
        float d0[8], d1[8];
#pragma unroll
        for (int e2 = 0; e2 < 8; e2++) {
            d0[e2] = dsm[e2 * 256 + cn];
            d1[e2] = dsm[e2 * 256 + cn + 1];
        }
#pragma unroll
        for (int mf = 0; mf < 4; mf++) {
#pragma unroll
            for (int hi = 0; hi < 2; hi++) {
                const int r = wr * 64 + mf * 16 + g + hi * 8;
                const float4* rp = (const float4*)(rsm + r * 8);
                const float4 rA = rp[0], rB = rp[1];
                float b0 = rA.x * d0[0] + rA.y * d0[1] + rA.z * d0[2] + rA.w * d0[3]
                         + rB.x * d0[4] + rB.y * d0[5] + rB.z * d0[6] + rB.w * d0[7];
                float b1 = rA.x * d1[0] + rA.y * d1[1] + rA.z * d1[2] + rA.w * d1[3]
                         + rB.x * d1[4] + rB.y * d1[5] + rB.z * d1[6] + rB.w * d1[7];
                float2 v;
                v.x = acc[mf][nf][hi * 2]     + b0;
                v.y = acc[mf][nf][hi * 2 + 1] + b1;
                *(float2*)(out + (size_t)(t0 + r) * H_DIM + h0 + cn) = v;
            }
        }
    }
}

extern "C" void kernel_launch(void* const* d_in, const int* in_sizes, int n_in,
                              void* d_out, int out_size)
{
    const float* hidden  = (const float*)d_in[0];
    const float* routing = (const float*)d_in[1];
    const float* gup     = (const float*)d_in[2];
    const float* gub     = (const float*)d_in[3];
    const float* down    = (const float*)d_in[4];
    const float* dpb     = (const float*)d_in[5];
    float* out = (float*)d_out;

    cudaFuncSetAttribute(k_gemm1, cudaFuncAttributeMaxDynamicSharedMemorySize, SMEM1);
    cudaFuncSetAttribute(k_gemm2, cudaFuncAttributeMaxDynamicSharedMemorySize, SMEM2);

    float *w1, *w2, *hs;
    cudaGetSymbolAddress((void**)&w1, g_w1);
    cudaGetSymbolAddress((void**)&w2, g_w2);
    cudaGetSymbolAddress((void**)&hs, g_hs);

    // pre-round all GEMM operands to tf32-representable fp32 (removes in-loop CVT)
    k_conv<<<(16777216 + 255) / 256, 256>>>((const float4*)gup,    (float4*)w1, 16777216);
    k_conv<<<( 8388608 + 255) / 256, 256>>>((const float4*)down,   (float4*)w2,  8388608);
    k_conv<<<( 1048576 + 255) / 256, 256>>>((const float4*)hidden, (float4*)hs,  1048576);

    dim3 g1(GU_COLS / BN1, T_DIM / BM, E_NUM);   // (32, 16, 8)
    k_gemm1<<<g1, NTHR, SMEM1>>>(routing, gub);

    dim3 g2(H_DIM / BN2, T_DIM / BM);            // (8, 16)
    k_gemm2<<<g2, NTHR, SMEM2>>>(routing, dpb, out);
}

// round 17
// speedup vs baseline: 2.0020x; 1.8811x over previous
#include <cuda_runtime.h>
#include <cuda_fp16.h>
#include <cstdint>

// GptOssExperts: out[t,h] = sum_e r[t,e]*(act(hs@gup[e]+gub[e])@dp[e]+dpb[e])
// Legacy mma.sync path (tcgen05 rejected by toolchain's sm_103 base target).
//  R17: switch operands tf32 -> FP16 (same 11-bit mantissa => same rel_err) and use
//       m16n8k16.f16 HMMA at 2x the tf32 MAC rate. Structures are R16's measured
//       optima with BK doubled (same slab shapes): gemm1 128x128, 2 CTA/SM, BK=64,
//       2-stage cp.async; gemm2 128x256, 1 CTA/SM, BK=128, mbarrier handshake.
//       A frags: ldmatrix.x4 (k-major). B frags: ldmatrix.x4.trans (k-major smem).

constexpr int T_DIM = 2048, H_DIM = 2048, I_DIM = 2048, E_NUM = 8;
constexpr int GU_COLS = 4096;          // 2*I
constexpr int KQ = E_NUM * I_DIM;      // 16384
constexpr int BM = 128;
constexpr int NTHR = 256;

// ---- gemm1 geometry (BN=128, BK=64 fp16, 2 stages, 2 CTA/SM) ----
constexpr int BN1 = 128, BK1 = 64;
constexpr int A_ROW1 = 144;            // 64 fp16 = 128B data + 16 pad (bank step 4r)
constexpr int B_ROW1 = 272;            // 128 fp16 = 256B data + 16 pad (bank step 4r)
constexpr int A_ST1 = BM * A_ROW1;               // 18432
constexpr int B_ST1 = BK1 * B_ROW1;              // 17408
constexpr int OFF_B1  = 2 * A_ST1;               // 36864
constexpr int OFF_AUX1 = OFF_B1 + 2 * B_ST1;     // 71680
constexpr int SMEM1 = OFF_AUX1 + 8448;           // 80128 (x2 CTAs)

// ---- gemm2 geometry (BN=256, BK=128 fp16, 2 stages, mbarrier) ----
constexpr int BN2 = 256, BK2 = 128;
constexpr int A_ROW2 = 272;            // 128 fp16 = 256B data + 16 pad
constexpr int B_ROW2 = 560;            // 256 fp16 = 512B data + 48 pad (bank step 12r)
constexpr int A_ST2 = BM * A_ROW2;               // 34816
constexpr int B_ST2 = BK2 * B_ROW2;              // 71680
constexpr int OFF_B2  = 2 * A_ST2;               // 69632
constexpr int OFF_AUX2 = OFF_B2 + 2 * B_ST2;     // 212992
constexpr int OFF_MBAR2 = OFF_AUX2 + 12288;      // 225280
constexpr int SMEM2 = OFF_AUX2 + 12544;          // 225536 (< 232448 opt-in)

// static scratch (device-global; allocation-free), all fp16
__device__ __half g_w1[67108864];      // gate_up_proj  (134 MB)
__device__ __half g_w2[33554432];      // down_proj     (67 MB)
__device__ __half g_hs[4194304];       // hidden_states (8 MB)
__device__ __half g_inter[33554432];   // routed-scaled intermediate [T][E*I] (67 MB)

__device__ __forceinline__ uint32_t cvta_smem(const void* p) {
    uint32_t a;
    asm("{ .reg .u64 t; cvta.to.shared.u64 t, %1; cvt.u32.u64 %0, t; }" : "=r"(a) : "l"(p));
    return a;
}
__device__ __forceinline__ void cp16(uint32_t saddr, const void* g) {
    asm volatile("cp.async.cg.shared.global [%0], [%1], 16;" :: "r"(saddr), "l"(g));
}
__device__ __forceinline__ void cp_commit() {
    asm volatile("cp.async.commit_group;" ::);
}
template <int N> __device__ __forceinline__ void cp_wait() {
    asm volatile("cp.async.wait_group %0;" :: "n"(N));
}
__device__ __forceinline__ void mbar_init(uint32_t addr, uint32_t cnt) {
    asm volatile("mbarrier.init.shared.b64 [%0], %1;" :: "r"(addr), "r"(cnt) : "memory");
}
__device__ __forceinline__ void mbar_arrive(uint32_t addr) {
    asm volatile("mbarrier.arrive.shared.b64 _, [%0];" :: "r"(addr) : "memory");
}
__device__ __forceinline__ void cp_arrive_noinc(uint32_t addr) {
    asm volatile("cp.async.mbarrier.arrive.noinc.shared.b64 [%0];" :: "r"(addr) : "memory");
}
__device__ __forceinline__ void mbar_wait(uint32_t addr, uint32_t parity) {
    asm volatile(
        "{\n\t.reg .pred P;\n\t"
        "WL%=:\n\t"
        "mbarrier.try_wait.parity.acquire.cta.shared::cta.b64 P, [%0], %1, 0x989680;\n\t"
        "@P bra WD%=;\n\t"
        "bra WL%=;\n\t"
        "WD%=:\n\t}"
        :: "r"(addr), "r"(parity) : "memory");
}
// m16n8k16 fp16 MMA, fp32 accumulate (2x tf32 MAC rate on legacy tensor path)
__device__ __forceinline__ void mma_f16(float (&c)[4],
    uint32_t a0, uint32_t a1, uint32_t a2, uint32_t a3, uint32_t b0, uint32_t b1)
{
    asm volatile(
        "mma.sync.aligned.m16n8k16.row.col.f32.f16.f16.f32 "
        "{%0,%1,%2,%3}, {%4,%5,%6,%7}, {%8,%9}, {%0,%1,%2,%3};"
        : "+f"(c[0]), "+f"(c[1]), "+f"(c[2]), "+f"(c[3])
        : "r"(a0), "r"(a1), "r"(a2), "r"(a3), "r"(b0), "r"(b1));
}
__device__ __forceinline__ void ldsm4(uint32_t (&r)[4], uint32_t addr) {
    asm volatile("ldmatrix.sync.aligned.m8n8.x4.shared.b16 {%0,%1,%2,%3}, [%4];"
                 : "=r"(r[0]), "=r"(r[1]), "=r"(r[2]), "=r"(r[3]) : "r"(addr));
}
__device__ __forceinline__ void ldsm4t(uint32_t& r0, uint32_t& r1, uint32_t& r2,
                                       uint32_t& r3, uint32_t addr) {
    asm volatile("ldmatrix.sync.aligned.m8n8.x4.trans.shared.b16 {%0,%1,%2,%3}, [%4];"
                 : "=r"(r0), "=r"(r1), "=r"(r2), "=r"(r3) : "r"(addr));
}

// ---- pre-pass: fp32 -> fp16 (rn) ----
__global__ __launch_bounds__(256) void k_convh(const float4* __restrict__ src,
                                               uint2* __restrict__ dst, int n4)
{
    int i = blockIdx.x * 256 + threadIdx.x;
    if (i < n4) {
        float4 v = src[i];
        __half2 h0 = __floats2half2_rn(v.x, v.y);
        __half2 h1 = __floats2half2_rn(v.z, v.w);
        uint2 o;
        o.x = *reinterpret_cast<uint32_t*>(&h0);
        o.y = *reinterpret_cast<uint32_t*>(&h1);
        dst[i] = o;
    }
}

// ============================ gemm1 core (fp16, BK=64, BN=128, 2-stage) ============================

__device__ __forceinline__ void load_frags1(uint32_t sAl, uint32_t sBl,
    int s, uint32_t (&a)[4][4], uint32_t (&b)[4][2])
{
#pragma unroll
    for (int mf = 0; mf < 4; mf++)
        ldsm4(a[mf], sAl + mf * (16 * A_ROW1) + s * 32);
    const uint32_t pb = sBl + s * (16 * B_ROW1);
    ldsm4t(b[0][0], b[0][1], b[1][0], b[1][1], pb);
    ldsm4t(b[2][0], b[2][1], b[3][0], b[3][1], pb + 32);
}
__device__ __forceinline__ void mma_step1(const uint32_t (&a)[4][4],
    const uint32_t (&b)[4][2], float (&acc)[4][4][4])
{
#pragma unroll
    for (int mf = 0; mf < 4; mf++)
#pragma unroll
        for (int nf = 0; nf < 4; nf++)
            mma_f16(acc[mf][nf], a[mf][0], a[mf][1], a[mf][2], a[mf][3],
                    b[nf][0], b[nf][1]);
}

struct Copier1 { const __half *ga0, *gb0; uint32_t sa0, sb0; int lda, ldb; };
__device__ __forceinline__ void init_copier1(Copier1& c, uint32_t smem_u32,
    const __half* __restrict__ A, int lda, const __half* __restrict__ B, int ldb)
{
    const int tid = threadIdx.x;
    c.lda = lda; c.ldb = ldb;
    int m = tid >> 3, kq = tid & 7;            // A: 8 chunks/row (128B), rows m+32j
    c.sa0 = smem_u32 + 0 + m * A_ROW1 + kq * 16;
    c.ga0 = A + (size_t)m * lda + kq * 8;
    int k = tid >> 4, nq = tid & 15;           // B: 16 chunks/row (256B), k-rows k+16j
    c.sb0 = smem_u32 + OFF_B1 + k * B_ROW1 + nq * 16;
    c.gb0 = B + (size_t)k * ldb + nq * 8;
}
__device__ __forceinline__ void issue_slab1(const Copier1& c, int i) {
    const int slot = i & 1;
    const size_t ka = (size_t)i * BK1;
#pragma unroll
    for (int j = 0; j < 4; j++)
        cp16(c.sa0 + slot * A_ST1 + j * 32 * A_ROW1, c.ga0 + ka + (size_t)j * 32 * c.lda);
#pragma unroll
    for (int j = 0; j < 4; j++)
        cp16(c.sb0 + slot * B_ST1 + j * 16 * B_ROW1, c.gb0 + (ka + 16 * j) * (size_t)c.ldb);
}

__device__ __forceinline__ void run_gemm1(
    const __half* __restrict__ A, int lda, const __half* __restrict__ B, int ldb,
    int nslab, uint32_t smem_u32, float (&acc)[4][4][4])
{
    const int tid = threadIdx.x, lane = tid & 31, wid = tid >> 5;
    const int wr = wid >> 2, wc = wid & 3;
    const int q = lane >> 3, r8 = lane & 7;

    const uint32_t sA_lane0 = smem_u32
        + (uint32_t)(wr * 64 + r8 + 8 * (q & 1)) * A_ROW1
        + (uint32_t)(q >> 1) * 16;
    const uint32_t sB_lane0 = smem_u32 + OFF_B1
        + (uint32_t)((q & 1) * 8 + r8) * B_ROW1
        + (uint32_t)(wc * 32 + (q >> 1) * 8) * 2;

    Copier1 c; init_copier1(c, smem_u32, A, lda, B, ldb);

    issue_slab1(c, 0); cp_commit();
    issue_slab1(c, 1); cp_commit();
    cp_wait<1>();
    __syncthreads();

    for (int i = 0; i < nslab; i++) {
        const int slot = i & 1;
        const uint32_t sAl = sA_lane0 + slot * A_ST1;
        const uint32_t sBl = sB_lane0 + slot * B_ST1;

        uint32_t a0[4][4], b0[4][2], a1[4][4], b1[4][2];
        load_frags1(sAl, sBl, 0, a0, b0);
        load_frags1(sAl, sBl, 1, a1, b1);
        mma_step1(a0, b0, acc);
        load_frags1(sAl, sBl, 2, a0, b0);
        mma_step1(a1, b1, acc);
        load_frags1(sAl, sBl, 3, a1, b1);
        __syncthreads();                 // all reads of slot(i) done; refill under MMA
        if (i + 2 < nslab) issue_slab1(c, i + 2);
        cp_commit();
        mma_step1(a0, b0, acc);
        mma_step1(a1, b1, acc);
        cp_wait<1>();
        __syncthreads();
    }
}

// ============================ gemm2 core (fp16, BK=128, BN=256, mbarrier) ============================

__device__ __forceinline__ void load_frags2(uint32_t sAl, uint32_t sBl,
    int s, uint32_t (&a)[4][4], uint32_t (&b)[8][2])
{
#pragma unroll
    for (int mf = 0; mf < 4; mf++)
        ldsm4(a[mf], sAl + mf * (16 * A_ROW2) + s * 32);
    const uint32_t pb = sBl + s * (16 * B_ROW2);
#pragma unroll
    for (int p = 0; p < 4; p++)
        ldsm4t(b[2 * p][0], b[2 * p][1], b[2 * p + 1][0], b[2 * p + 1][1], pb + p * 32);
}
__device__ __forceinline__ void mma_step2(const uint32_t (&a)[4][4],
    const uint32_t (&b)[8][2], float (&acc)[4][8][4])
{
#pragma unroll
    for (int mf = 0; mf < 4; mf++)
#pragma unroll
        for (int nf = 0; nf < 8; nf++)
            mma_f16(acc[mf][nf], a[mf][0], a[mf][1], a[mf][2], a[mf][3],
                    b[nf][0], b[nf][1]);
}

struct Copier2 { const __half *ga0, *gb0; uint32_t sa0, sb0; int lda, ldb; };
__device__ __forceinline__ void init_copier2(Copier2& c, uint32_t smem_u32,
    const __half* __restrict__ A, int lda, const __half* __restrict__ B, int ldb)
{
    const int tid = threadIdx.x;
    c.lda = lda; c.ldb = ldb;
    int m = tid >> 4, kq = tid & 15;           // A: 16 chunks/row (256B), rows m+16j
    c.sa0 = smem_u32 + 0 + m * A_ROW2 + kq * 16;
    c.ga0 = A + (size_t)m * lda + kq * 8;
    int k = tid >> 5, nq = tid & 31;           // B: 32 chunks/row (512B), k-rows k+8j
    c.sb0 = smem_u32 + OFF_B2 + k * B_ROW2 + nq * 16;
    c.gb0 = B + (size_t)k * ldb + nq * 8;
}
__device__ __forceinline__ void issue_slab2(const Copier2& c, int i) {
    const int slot = i & 1;
    const size_t ka = (size_t)i * BK2;
#pragma unroll
    for (int j = 0; j < 8; j++)
        cp16(c.sa0 + slot * A_ST2 + j * 16 * A_ROW2, c.ga0 + ka + (size_t)j * 16 * c.lda);
#pragma unroll
    for (int j = 0; j < 16; j++)
        cp16(c.sb0 + slot * B_ST2 + j * 8 * B_ROW2, c.gb0 + (ka + 8 * j) * (size_t)c.ldb);
}

__device__ __forceinline__ void run_gemm2(
    const __half* __restrict__ A, int lda, const __half* __restrict__ B, int ldb,
    int nslab, uint32_t smem_u32, float (&acc)[4][8][4])
{
    const int tid = threadIdx.x, lane = tid & 31, wid = tid >> 5;
    const int wr = wid >> 2, wc = wid & 3;
    const int q = lane >> 3, r8 = lane & 7;

    const uint32_t sA_lane0 = smem_u32
        + (uint32_t)(wr * 64 + r8 + 8 * (q & 1)) * A_ROW2
        + (uint32_t)(q >> 1) * 16;
    const uint32_t sB_lane0 = smem_u32 + OFF_B2
        + (uint32_t)((q & 1) * 8 + r8) * B_ROW2
        + (uint32_t)(wc * 64 + (q >> 1) * 8) * 2;

    const uint32_t mb_fill = smem_u32 + OFF_MBAR2;
    const uint32_t mb_read = smem_u32 + OFF_MBAR2 + 16;
    if (tid == 0) {
        mbar_init(mb_fill,      NTHR); mbar_init(mb_fill + 8, NTHR);
        mbar_init(mb_read,      NTHR); mbar_init(mb_read + 8, NTHR);
    }
    __syncthreads();

    Copier2 c; init_copier2(c, smem_u32, A, lda, B, ldb);

    issue_slab2(c, 0); cp_arrive_noinc(mb_fill);
    issue_slab2(c, 1); cp_arrive_noinc(mb_fill + 8);

    for (int i = 0; i < nslab; i++) {
        const int slot = i & 1;
        const uint32_t par = (uint32_t)((i >> 1) & 1);
        const uint32_t sAl = sA_lane0 + slot * A_ST2;
        const uint32_t sBl = sB_lane0 + slot * B_ST2;

        mbar_wait(mb_fill + slot * 8, par);      // slab i landed + visible

        uint32_t a0[4][4], b0[8][2], a1[4][4], b1[8][2];
        load_frags2(sAl, sBl, 0, a0, b0);
        load_frags2(sAl, sBl, 1, a1, b1);
#pragma unroll
        for (int s = 0; s < 6; s += 2) {
            mma_step2(a0, b0, acc);
            load_frags2(sAl, sBl, s + 2, a0, b0);
            mma_step2(a1, b1, acc);
            load_frags2(sAl, sBl, s + 3, a1, b1);
        }
        mbar_arrive(mb_read + slot * 8);         // all reads of slot(i) issued
        mma_step2(a0, b0, acc);
        if (i + 2 < nslab) {
            mbar_wait(mb_read + slot * 8, par);  // all warps done reading slot; refill
            issue_slab2(c, i + 2);
            cp_arrive_noinc(mb_fill + slot * 8);
        }
        mma_step2(a1, b1, acc);
    }
}

// ================= Stage 1: gu = hs @ gup[e] + gub; GLU; fold routing -> g_inter =================
__global__ __launch_bounds__(NTHR, 2) void k_gemm1(
    const float* __restrict__ routing, const float* __restrict__ gub)
{
    extern __shared__ char smem[];
    const uint32_t sb = cvta_smem(smem);
    const int tid = threadIdx.x, lane = tid & 31, wid = tid >> 5;
    const int wr = wid >> 2, wc = wid & 3, g = lane >> 2, t4 = lane & 3;
    const int e = blockIdx.z, t0 = blockIdx.y * BM, j0 = blockIdx.x * BN1;

    float* rs   = (float*)(smem + OFF_AUX1);        // [128]
    float* bias = (float*)(smem + OFF_AUX1 + 512);  // [128]
    if (tid < 128) rs[tid] = routing[(size_t)(t0 + tid) * E_NUM + e];
    else           bias[tid - 128] = gub[(size_t)e * GU_COLS + j0 + (tid - 128)];
    // visibility covered by the __syncthreads inside run_gemm1

    float acc[4][4][4] = {};
    run_gemm1(g_hs + (size_t)t0 * H_DIM, H_DIM,
              g_w1 + (size_t)e * H_DIM * GU_COLS + j0, GU_COLS,
              H_DIM / BK1, sb, acc);

#pragma unroll
    for (int mf = 0; mf < 4; mf++) {
#pragma unroll
        for (int hi = 0; hi < 2; hi++) {
            const int r = wr * 64 + mf * 16 + g + hi * 8;
            const float rv = rs[r];
            __half* grow = g_inter + (size_t)(t0 + r) * KQ + (size_t)e * I_DIM + (j0 >> 1);
#pragma unroll
            for (int nf = 0; nf < 4; nf++) {
                const int cn = wc * 32 + nf * 8 + 2 * t4;  // even gu col = gate; +1 = up
                float gate = acc[mf][nf][hi * 2]     + bias[cn];
                float up   = acc[mf][nf][hi * 2 + 1] + bias[cn + 1];
                gate = fminf(gate, 7.0f);
                up   = fminf(fmaxf(up, -7.0f), 7.0f);
                const float glu = gate / (1.0f + __expf(-1.702f * gate));
                grow[cn >> 1] = __float2half_rn((up + 1.0f) * glu * rv);
            }
        }
    }
}

// ================= Stage 2: out = inter'[T,E*I] @ down[E*I,H] + routing @ dpb =================
__global__ __launch_bounds__(NTHR, 1) void k_gemm2(
    const float* __restrict__ routing, const float* __restrict__ dpb,
    float* __restrict__ out)
{
    extern __shared__ char smem[];
    const uint32_t sb = cvta_smem(smem);
    const int tid = threadIdx.x, lane = tid & 31, wid = tid >> 5;
    const int wr = wid >> 2, wc = wid & 3, g = lane >> 2, t4 = lane & 3;
    const int t0 = blockIdx.y * BM, h0 = blockIdx.x * BN2;

    float* rsm = (float*)(smem + OFF_AUX2);         // [128][8]
    float* dsm = (float*)(smem + OFF_AUX2 + 4096);  // [8][256]
#pragma unroll
    for (int j = 0; j < 4; j++) {
        int idx = tid + NTHR * j;
        rsm[idx] = routing[(size_t)t0 * E_NUM + idx];
    }
#pragma unroll
    for (int j = 0; j < 8; j++) {
        int idx = tid + NTHR * j;
        dsm[idx] = dpb[(size_t)(idx >> 8) * H_DIM + h0 + (idx & 255)];
    }
    // visibility covered by the __syncthreads inside run_gemm2

    float acc[4][8][4] = {};
    run_gemm2(g_inter + (size_t)t0 * KQ, KQ,
              g_w2 + h0, H_DIM,
              KQ / BK2, sb, acc);

#pragma unroll
    for (int nf = 0; nf < 8; nf++) {
        const int cn = wc * 64 + nf * 8 + 2 * t4;
        float d0[8], d1[8];
#pragma unroll
        for (int e2 = 0; e2 < 8; e2++) {
            d0[e2] = dsm[e2 * 256 + cn];
            d1[e2] = dsm[e2 * 256 + cn + 1];
        }
#pragma unroll
        for (int mf = 0; mf < 4; mf++) {
#pragma unroll
            for (int hi = 0; hi < 2; hi++) {
                const int r = wr * 64 + mf * 16 + g + hi * 8;
                const float4* rp = (const float4*)(rsm + r * 8);
                const float4 rA = rp[0], rB = rp[1];
                float b0 = rA.x * d0[0] + rA.y * d0[1] + rA.z * d0[2] + rA.w * d0[3]
                         + rB.x * d0[4] + rB.y * d0[5] + rB.z * d0[6] + rB.w * d0[7];
                float b1 = rA.x * d1[0] + rA.y * d1[1] + rA.z * d1[2] + rA.w * d1[3]
                         + rB.x * d1[4] + rB.y * d1[5] + rB.z * d1[6] + rB.w * d1[7];
                float2 v;
                v.x = acc[mf][nf][hi * 2]     + b0;
                v.y = acc[mf][nf][hi * 2 + 1] + b1;
                *(float2*)(out + (size_t)(t0 + r) * H_DIM + h0 + cn) = v;
            }
        }
    }
}

extern "C" void kernel_launch(void* const* d_in, const int* in_sizes, int n_in,
                              void* d_out, int out_size)
{
    const float* hidden  = (const float*)d_in[0];
    const float* routing = (const float*)d_in[1];
    const float* gup     = (const float*)d_in[2];
    const float* gub     = (const float*)d_in[3];
    const float* down    = (const float*)d_in[4];
    const float* dpb     = (const float*)d_in[5];
    float* out = (float*)d_out;

    cudaFuncSetAttribute(k_gemm1, cudaFuncAttributeMaxDynamicSharedMemorySize, SMEM1);
    cudaFuncSetAttribute(k_gemm2, cudaFuncAttributeMaxDynamicSharedMemorySize, SMEM2);

    __half *w1, *w2, *hs;
    cudaGetSymbolAddress((void**)&w1, g_w1);
    cudaGetSymbolAddress((void**)&w2, g_w2);
    cudaGetSymbolAddress((void**)&hs, g_hs);

    // pre-convert all GEMM operands fp32 -> fp16 (rn)
    k_convh<<<(16777216 + 255) / 256, 256>>>((const float4*)gup,    (uint2*)w1, 16777216);
    k_convh<<<( 8388608 + 255) / 256, 256>>>((const float4*)down,   (uint2*)w2,  8388608);
    k_convh<<<( 1048576 + 255) / 256, 256>>>((const float4*)hidden, (uint2*)hs,  1048576);

    dim3 g1(GU_COLS / BN1, T_DIM / BM, E_NUM);   // (32, 16, 8)
    k_gemm1<<<g1, NTHR, SMEM1>>>(routing, gub);

    dim3 g2(H_DIM / BN2, T_DIM / BM);            // (8, 16)
    k_gemm2<<<g2, NTHR, SMEM2>>>(routing, dpb, out);
}